// round 9
// baseline (speedup 1.0000x reference)
#include <cuda_runtime.h>
#include <cuda_bf16.h>
#include <cstdint>
#include <stdint.h>
#include <math.h>

#define CAMS   6
#define NQ     6400
#define EMBED  256
#define HEADS  8
#define LEVELS 4
#define POINTS 8
#define DEPTH  4
#define DH     32
#define FLEN   14960
#define MROWS  (CAMS * FLEN)   /* 89760 */
#define NOFFAW 768             /* 512 offsets + 256 aw logits */
#define NTILES 702             /* row tiles of 128 for vproj */
#define PGRID  176             /* persistent CTAs per column half */

// ---------------- static device scratch (no allocations allowed) ----------------
__device__ __nv_bfloat16 g_vproj [(size_t)MROWS * EMBED];      // ~46 MB  [c][f][256]
__device__ float         g_offaw [(size_t)NQ * NOFFAW];        // ~20 MB  [n][768]
__device__ __nv_bfloat16 g_outcam[(size_t)CAMS * NQ * EMBED];  // ~20 MB  [c][n][256]
__device__ int   g_maskq [CAMS * NQ];
__device__ float g_invcnt[NQ];

// ======================== shared mma tile machinery =====================
#define BP 264                 /* Bs pitch in bf16 (256 + 8) */
#define AP 40                  /* As pitch in bf16 (32 + 8)  */
#define VP_SMEM (128 * BP * 2 + 128 * AP * 2)   /* 77824 B */

__device__ __forceinline__ uint32_t smem_cast(const void* p) {
    uint32_t a;
    asm("{ .reg .u64 t; cvta.to.shared.u64 t, %1; cvt.u32.u64 %0, t; }" : "=r"(a) : "l"(p));
    return a;
}

#define LDSM_X4(R0, R1, R2, R3, A) \
    asm volatile("ldmatrix.sync.aligned.m8n8.x4.shared.b16 {%0,%1,%2,%3}, [%4];" \
        : "=r"(R0), "=r"(R1), "=r"(R2), "=r"(R3) : "r"(A))

__device__ __forceinline__ void mma_bf16(float* c, const uint32_t* a, const uint32_t* b)
{
    asm volatile(
        "mma.sync.aligned.m16n8k16.row.col.f32.bf16.bf16.f32 "
        "{%0,%1,%2,%3}, {%4,%5,%6,%7}, {%8,%9}, {%0,%1,%2,%3};"
        : "+f"(c[0]), "+f"(c[1]), "+f"(c[2]), "+f"(c[3])
        : "r"(a[0]), "r"(a[1]), "r"(a[2]), "r"(a[3]), "r"(b[0]), "r"(b[1]));
}

// inner-loop body shared by all three GEMMs, ldmatrix edition.
// A fragment: canonical x4 (mats {rows, rows+8} x {k, k+8}).
// B [n][k] row-major, non-trans x4 covers two n-tiles x both k-halves.
__device__ __forceinline__ void mma_chunk(
    uint32_t As_u32, uint32_t Bs_u32, int kc,
    int wm, int wn, int lane, float acc[2][8][4])
{
    const int a_row  = wm * 32 + (lane & 7) + ((lane >> 3) & 1) * 8;
    const int a_col  = (lane >> 4) * 8;
    const uint32_t a_base = As_u32 + (uint32_t)((a_row * AP + a_col) * 2);
    const int b_row  = wn * 64 + ((lane >> 4) * 8) + (lane & 7);
    const int b_col  = ((lane >> 3) & 1) * 8;
    const uint32_t b_base = Bs_u32 + (uint32_t)((b_row * BP + kc * 32 + b_col) * 2);

#pragma unroll
    for (int ks = 0; ks < 32; ks += 16) {
        uint32_t a[2][4], b[8][2];
        LDSM_X4(a[0][0], a[0][1], a[0][2], a[0][3], a_base + (uint32_t)(ks * 2));
        LDSM_X4(a[1][0], a[1][1], a[1][2], a[1][3], a_base + (uint32_t)((16 * AP + ks) * 2));
#pragma unroll
        for (int p = 0; p < 4; p++) {
            LDSM_X4(b[2 * p][0], b[2 * p][1], b[2 * p + 1][0], b[2 * p + 1][1],
                    b_base + (uint32_t)((p * 16 * BP + ks) * 2));
        }
#pragma unroll
        for (int mi = 0; mi < 2; mi++)
#pragma unroll
            for (int ni = 0; ni < 8; ni++)
                mma_bf16(acc[mi][ni], a[mi], b[ni]);
    }
}

// =======================================================================
// GEMM 1: vproj[r][n] = value_row(r) @ Wv[:, n] + bv[n]  (bf16 out)
// Persistent CTAs: B slice loaded ONCE, then loop over row tiles.
// =======================================================================
__global__ __launch_bounds__(256) void vproj_mma_kernel(
    const float* __restrict__ value, const float* __restrict__ Wv,
    const float* __restrict__ bv)
{
    extern __shared__ char smem[];
    __nv_bfloat16* Bs = reinterpret_cast<__nv_bfloat16*>(smem);
    __nv_bfloat16* As = reinterpret_cast<__nv_bfloat16*>(smem + 128 * BP * 2);
    const uint32_t Bs_u32 = smem_cast(Bs);
    const uint32_t As_u32 = smem_cast(As);

    const int tid  = threadIdx.x;
    const int wid  = tid >> 5;
    const int lane = tid & 31;
    const int wm   = wid >> 1;
    const int wn   = wid & 1;
    const int n0   = blockIdx.x * 128;
    const int qr = lane >> 2, qc = lane & 3;

    // ---- B fill: once per CTA ----
#pragma unroll
    for (int i = 0; i < 64; i++) {
        int u  = i * 256 + tid;
        int k  = u >> 6;
        int np = u & 63;
        float2 w = *reinterpret_cast<const float2*>(Wv + (size_t)k * EMBED + n0 + np * 2);
        Bs[(np * 2 + 0) * BP + k] = __float2bfloat16(w.x);
        Bs[(np * 2 + 1) * BP + k] = __float2bfloat16(w.y);
    }

    for (int t = blockIdx.y; t < NTILES; t += PGRID) {
        const int row0 = t * 128;

        const float* aptr[4];
        int arows[4], akq[4];
#pragma unroll
        for (int i = 0; i < 4; i++) {
            int u   = i * 256 + tid;
            arows[i] = u >> 3;
            akq[i]  = (u & 7) * 4;
            int r = row0 + arows[i];
            if (r >= MROWS) r = MROWS - 1;
            int c = r / FLEN;
            int f = r - c * FLEN;
            aptr[i] = value + ((size_t)f * CAMS + c) * EMBED + akq[i];
        }

        float acc[2][8][4];
#pragma unroll
        for (int mi = 0; mi < 2; mi++)
#pragma unroll
            for (int ni = 0; ni < 8; ni++)
#pragma unroll
                for (int j = 0; j < 4; j++) acc[mi][ni][j] = 0.f;

        float4 v[4];
#pragma unroll
        for (int i = 0; i < 4; i++) v[i] = *reinterpret_cast<const float4*>(aptr[i]);

        for (int kc = 0; kc < 8; kc++) {
            __syncthreads();
#pragma unroll
            for (int i = 0; i < 4; i++) {
                __nv_bfloat162 p0, p1;
                p0.x = __float2bfloat16(v[i].x); p0.y = __float2bfloat16(v[i].y);
                p1.x = __float2bfloat16(v[i].z); p1.y = __float2bfloat16(v[i].w);
                uint2 st;
                st.x = *reinterpret_cast<uint32_t*>(&p0);
                st.y = *reinterpret_cast<uint32_t*>(&p1);
                *reinterpret_cast<uint2*>(&As[arows[i] * AP + akq[i]]) = st;
            }
            __syncthreads();
            if (kc < 7) {
#pragma unroll
                for (int i = 0; i < 4; i++)
                    v[i] = *reinterpret_cast<const float4*>(aptr[i] + (kc + 1) * 32);
            }
            mma_chunk(As_u32, Bs_u32, kc, wm, wn, lane, acc);
        }

#pragma unroll
        for (int mi = 0; mi < 2; mi++) {
            int rb = row0 + wm * 32 + mi * 16;
#pragma unroll
            for (int half = 0; half < 2; half++) {
                int r = rb + qr + half * 8;
                if (r >= MROWS) continue;
                __nv_bfloat16* dst = g_vproj + (size_t)r * EMBED;
#pragma unroll
                for (int ni = 0; ni < 8; ni++) {
                    int n = n0 + wn * 64 + ni * 8 + qc * 2;
                    __nv_bfloat162 o;
                    o.x = __float2bfloat16(acc[mi][ni][half * 2 + 0] + bv[n]);
                    o.y = __float2bfloat16(acc[mi][ni][half * 2 + 1] + bv[n + 1]);
                    *reinterpret_cast<__nv_bfloat162*>(dst + n) = o;
                }
            }
        }
    }
}

// =======================================================================
// GEMM 2: offaw[r][col] = (query+qpos)(r,:) @ [Wso|Waw](:,col) + bias
// =======================================================================
__global__ __launch_bounds__(256) void offaw_mma_kernel(
    const float* __restrict__ query, const float* __restrict__ qpos,
    const float* __restrict__ Wso, const float* __restrict__ bso,
    const float* __restrict__ Waw, const float* __restrict__ baw)
{
    extern __shared__ char smem[];
    __nv_bfloat16* Bs = reinterpret_cast<__nv_bfloat16*>(smem);
    __nv_bfloat16* As = reinterpret_cast<__nv_bfloat16*>(smem + 128 * BP * 2);
    const uint32_t Bs_u32 = smem_cast(Bs);
    const uint32_t As_u32 = smem_cast(As);

    const int tid  = threadIdx.x;
    const int wid  = tid >> 5;
    const int lane = tid & 31;
    const int wm   = wid >> 1;
    const int wn   = wid & 1;
    const int n0   = blockIdx.x * 128;        // 0..640
    const int qr = lane >> 2, qc = lane & 3;

    const bool is_so   = (n0 < 512);
    const float* Bsrc  = is_so ? Wso : Waw;
    const int    bstr  = is_so ? 512 : 256;
    const int    bcol0 = is_so ? n0 : (n0 - 512);

#pragma unroll
    for (int i = 0; i < 64; i++) {
        int u  = i * 256 + tid;
        int k  = u >> 6;
        int np = u & 63;
        float2 w = *reinterpret_cast<const float2*>(Bsrc + (size_t)k * bstr + bcol0 + np * 2);
        Bs[(np * 2 + 0) * BP + k] = __float2bfloat16(w.x);
        Bs[(np * 2 + 1) * BP + k] = __float2bfloat16(w.y);
    }

    for (int t = blockIdx.y; t < 50; t += 25) {
        const int row0 = t * 128;

        float acc[2][8][4];
#pragma unroll
        for (int mi = 0; mi < 2; mi++)
#pragma unroll
            for (int ni = 0; ni < 8; ni++)
#pragma unroll
                for (int j = 0; j < 4; j++) acc[mi][ni][j] = 0.f;

        for (int kc = 0; kc < 8; kc++) {
            __syncthreads();
#pragma unroll
            for (int i = 0; i < 4; i++) {
                int u   = i * 256 + tid;
                int row = u >> 3;
                int kq  = (u & 7) * 4;
                int r = row0 + row;
                float4 a = *reinterpret_cast<const float4*>(query + (size_t)r * EMBED + kc * 32 + kq);
                float4 p = *reinterpret_cast<const float4*>(qpos  + (size_t)r * EMBED + kc * 32 + kq);
                __nv_bfloat162 p0, p1;
                p0.x = __float2bfloat16(a.x + p.x); p0.y = __float2bfloat16(a.y + p.y);
                p1.x = __float2bfloat16(a.z + p.z); p1.y = __float2bfloat16(a.w + p.w);
                uint2 st;
                st.x = *reinterpret_cast<uint32_t*>(&p0);
                st.y = *reinterpret_cast<uint32_t*>(&p1);
                *reinterpret_cast<uint2*>(&As[row * AP + kq]) = st;
            }
            __syncthreads();
            mma_chunk(As_u32, Bs_u32, kc, wm, wn, lane, acc);
        }

#pragma unroll
        for (int mi = 0; mi < 2; mi++) {
            int rb = row0 + wm * 32 + mi * 16;
#pragma unroll
            for (int half = 0; half < 2; half++) {
                int r = rb + qr + half * 8;
                float* dst = g_offaw + (size_t)r * NOFFAW;
#pragma unroll
                for (int ni = 0; ni < 8; ni++) {
                    int col = n0 + wn * 64 + ni * 8 + qc * 2;
                    float b0 = (col < 512) ? bso[col] : baw[col - 512];
                    float b1 = (col + 1 < 512) ? bso[col + 1] : baw[col + 1 - 512];
                    float2 o;
                    o.x = acc[mi][ni][half * 2 + 0] + b0;
                    o.y = acc[mi][ni][half * 2 + 1] + b1;
                    *reinterpret_cast<float2*>(dst + col) = o;
                }
            }
        }
    }
}

// =======================================================================
// mask / count
// =======================================================================
__global__ void mask_kernel(const unsigned int* __restrict__ bm)
{
    int n = blockIdx.x * blockDim.x + threadIdx.x;
    if (n >= NQ) return;
    int cnt = 0;
#pragma unroll
    for (int c = 0; c < CAMS; c++) {
        const unsigned int* q = bm + ((size_t)c * NQ + n) * DEPTH;
        unsigned int any = q[0] | q[1] | q[2] | q[3];
        int m = any ? 1 : 0;
        g_maskq[c * NQ + n] = m;
        cnt += m;
    }
    g_invcnt[n] = 1.0f / fmaxf((float)cnt, 1.0f);
}

// =======================================================================
// MSDA sampler, two-phase, softmax fused (quarter-warp gather)
// =======================================================================
__global__ __launch_bounds__(256) void sampler_kernel(const float* __restrict__ refcam)
{
    const int bx = blockIdx.x;           // c*NQ + n
    const int c  = bx / NQ;
    const int n  = bx - c * NQ;
    __shared__ float sref[8];
    __shared__ int   smask;
    __shared__ int4   sidx[256];
    __shared__ float4 swt [256];

    const int tid = threadIdx.x;
    if (tid == 0) smask = g_maskq[bx];
    if (tid < 8) sref[tid] = refcam[(size_t)bx * 8 + tid];
    __syncthreads();
    if (!smask) {
        g_outcam[(size_t)bx * EMBED + tid] = __float2bfloat16(0.f);
        return;
    }

    // ---- phase 1: softmax + coordinates & weights (warp == head) ----
    {
        const int s = tid & 31;          // sample within head
        const int l = s >> 3;
        const int d = s & 3;
        const int   cWl[4] = {176, 88, 44, 22};
        const int   cHl[4] = {64, 32, 16, 8};
        const int   cls[4] = {0, 11264, 14080, 14784};
        const int Wl = cWl[l], Hl = cHl[l], ls = cls[l];

        float2 off   = *reinterpret_cast<const float2*>(g_offaw + (size_t)n * NOFFAW + 2 * tid);
        float  logit = g_offaw[(size_t)n * NOFFAW + 512 + tid];

        float m = logit;
#pragma unroll
        for (int o = 16; o; o >>= 1) m = fmaxf(m, __shfl_xor_sync(0xffffffffu, m, o));
        float e = __expf(logit - m);
        float ssum = e;
#pragma unroll
        for (int o = 16; o; o >>= 1) ssum += __shfl_xor_sync(0xffffffffu, ssum, o);
        float aw = e / ssum;

        float x = sref[d * 2 + 0] * (float)Wl + off.x - 0.5f;
        float y = sref[d * 2 + 1] * (float)Hl + off.y - 0.5f;
        float x0f = floorf(x), y0f = floorf(y);
        float fx = x - x0f, fy = y - y0f;
        int x0 = (int)x0f, y0 = (int)y0f;
        int x1 = x0 + 1,   y1 = y0 + 1;

        float vx0 = ((unsigned)x0 < (unsigned)Wl) ? 1.f : 0.f;
        float vx1 = ((unsigned)x1 < (unsigned)Wl) ? 1.f : 0.f;
        float vy0 = ((unsigned)y0 < (unsigned)Hl) ? 1.f : 0.f;
        float vy1 = ((unsigned)y1 < (unsigned)Hl) ? 1.f : 0.f;

        int cx0 = min(max(x0, 0), Wl - 1);
        int cx1 = min(max(x1, 0), Wl - 1);
        int cy0 = min(max(y0, 0), Hl - 1);
        int cy1 = min(max(y1, 0), Hl - 1);

        int4 id;
        id.x = ls + cy0 * Wl + cx0;
        id.y = ls + cy0 * Wl + cx1;
        id.z = ls + cy1 * Wl + cx0;
        id.w = ls + cy1 * Wl + cx1;
        float4 w;
        w.x = (1.f - fx) * (1.f - fy) * aw * vx0 * vy0;
        w.y = fx * (1.f - fy) * aw * vx1 * vy0;
        w.z = (1.f - fx) * fy * aw * vx0 * vy1;
        w.w = fx * fy * aw * vx1 * vy1;
        sidx[tid] = id;
        swt [tid] = w;
    }
    __syncthreads();

    // ---- phase 2: quarter-warp vectorized gather ----
    {
        const int h    = tid >> 5;
        const int lane = tid & 31;
        const int g    = lane >> 3;      // group 0..3: sample s = it*4 + g
        const int j    = lane & 7;       // channel quad
        const uint16_t* vb = reinterpret_cast<const uint16_t*>(
            g_vproj + (size_t)c * FLEN * EMBED + h * DH + j * 4);
        float a0 = 0.f, a1 = 0.f, a2 = 0.f, a3 = 0.f;
#pragma unroll 2
        for (int it = 0; it < 8; it++) {
            int s = it * 4 + g;
            int4   id = sidx[h * 32 + s];
            float4 w  = swt [h * 32 + s];
            uint2 r0 = *reinterpret_cast<const uint2*>(vb + (size_t)id.x * EMBED);
            uint2 r1 = *reinterpret_cast<const uint2*>(vb + (size_t)id.y * EMBED);
            uint2 r2 = *reinterpret_cast<const uint2*>(vb + (size_t)id.z * EMBED);
            uint2 r3 = *reinterpret_cast<const uint2*>(vb + (size_t)id.w * EMBED);
            __nv_bfloat162 p;
            p = *reinterpret_cast<__nv_bfloat162*>(&r0.x);
            a0 = fmaf(w.x, __bfloat162float(p.x), a0); a1 = fmaf(w.x, __bfloat162float(p.y), a1);
            p = *reinterpret_cast<__nv_bfloat162*>(&r0.y);
            a2 = fmaf(w.x, __bfloat162float(p.x), a2); a3 = fmaf(w.x, __bfloat162float(p.y), a3);
            p = *reinterpret_cast<__nv_bfloat162*>(&r1.x);
            a0 = fmaf(w.y, __bfloat162float(p.x), a0); a1 = fmaf(w.y, __bfloat162float(p.y), a1);
            p = *reinterpret_cast<__nv_bfloat162*>(&r1.y);
            a2 = fmaf(w.y, __bfloat162float(p.x), a2); a3 = fmaf(w.y, __bfloat162float(p.y), a3);
            p = *reinterpret_cast<__nv_bfloat162*>(&r2.x);
            a0 = fmaf(w.z, __bfloat162float(p.x), a0); a1 = fmaf(w.z, __bfloat162float(p.y), a1);
            p = *reinterpret_cast<__nv_bfloat162*>(&r2.y);
            a2 = fmaf(w.z, __bfloat162float(p.x), a2); a3 = fmaf(w.z, __bfloat162float(p.y), a3);
            p = *reinterpret_cast<__nv_bfloat162*>(&r3.x);
            a0 = fmaf(w.w, __bfloat162float(p.x), a0); a1 = fmaf(w.w, __bfloat162float(p.y), a1);
            p = *reinterpret_cast<__nv_bfloat162*>(&r3.y);
            a2 = fmaf(w.w, __bfloat162float(p.x), a2); a3 = fmaf(w.w, __bfloat162float(p.y), a3);
        }
        a0 += __shfl_xor_sync(0xffffffffu, a0, 8);
        a1 += __shfl_xor_sync(0xffffffffu, a1, 8);
        a2 += __shfl_xor_sync(0xffffffffu, a2, 8);
        a3 += __shfl_xor_sync(0xffffffffu, a3, 8);
        a0 += __shfl_xor_sync(0xffffffffu, a0, 16);
        a1 += __shfl_xor_sync(0xffffffffu, a1, 16);
        a2 += __shfl_xor_sync(0xffffffffu, a2, 16);
        a3 += __shfl_xor_sync(0xffffffffu, a3, 16);
        if (g == 0) {
            __nv_bfloat162 o0, o1;
            o0.x = __float2bfloat16(a0); o0.y = __float2bfloat16(a1);
            o1.x = __float2bfloat16(a2); o1.y = __float2bfloat16(a3);
            uint2 st;
            st.x = *reinterpret_cast<uint32_t*>(&o0);
            st.y = *reinterpret_cast<uint32_t*>(&o1);
            *reinterpret_cast<uint2*>(
                g_outcam + (size_t)bx * EMBED + h * DH + j * 4) = st;
        }
    }
}

// =======================================================================
// GEMM 3 (final mma): A[r][k] = invcnt[r]*sum_c outcam[c][r][k] (bf16)
// out = A @ Wout + bout + query.  M=6400, N=256, K=256.
// =======================================================================
__global__ __launch_bounds__(256) void final_mma_kernel(
    const float* __restrict__ query, const float* __restrict__ Wout,
    const float* __restrict__ bout, float* __restrict__ out)
{
    extern __shared__ char smem[];
    __nv_bfloat16* Bs = reinterpret_cast<__nv_bfloat16*>(smem);
    __nv_bfloat16* As = reinterpret_cast<__nv_bfloat16*>(smem + 128 * BP * 2);
    const uint32_t Bs_u32 = smem_cast(Bs);
    const uint32_t As_u32 = smem_cast(As);

    const int tid  = threadIdx.x;
    const int wid  = tid >> 5;
    const int lane = tid & 31;
    const int wm   = wid >> 1;
    const int wn   = wid & 1;
    const int n0   = blockIdx.x * 128;
    const int row0 = blockIdx.y * 128;
    const int qr = lane >> 2, qc = lane & 3;

#pragma unroll
    for (int i = 0; i < 64; i++) {
        int u  = i * 256 + tid;
        int k  = u >> 6;
        int np = u & 63;
        float2 w = *reinterpret_cast<const float2*>(Wout + (size_t)k * EMBED + n0 + np * 2);
        Bs[(np * 2 + 0) * BP + k] = __float2bfloat16(w.x);
        Bs[(np * 2 + 1) * BP + k] = __float2bfloat16(w.y);
    }

    float acc[2][8][4];
#pragma unroll
    for (int mi = 0; mi < 2; mi++)
#pragma unroll
        for (int ni = 0; ni < 8; ni++)
#pragma unroll
            for (int j = 0; j < 4; j++) acc[mi][ni][j] = 0.f;

    for (int kc = 0; kc < 8; kc++) {
        __syncthreads();
#pragma unroll
        for (int i = 0; i < 4; i++) {
            int u   = i * 256 + tid;
            int row = u >> 3;
            int kq  = (u & 7) * 4;
            int r = row0 + row;
            float inv = g_invcnt[r];
            float s0 = 0.f, s1 = 0.f, s2 = 0.f, s3 = 0.f;
#pragma unroll
            for (int c = 0; c < CAMS; c++) {
                const __nv_bfloat16* src =
                    g_outcam + ((size_t)c * NQ + r) * EMBED + kc * 32 + kq;
                uint2 u2 = *reinterpret_cast<const uint2*>(src);
                __nv_bfloat162 p0 = *reinterpret_cast<__nv_bfloat162*>(&u2.x);
                __nv_bfloat162 p1 = *reinterpret_cast<__nv_bfloat162*>(&u2.y);
                s0 += __bfloat162float(p0.x); s1 += __bfloat162float(p0.y);
                s2 += __bfloat162float(p1.x); s3 += __bfloat162float(p1.y);
            }
            __nv_bfloat162 q0, q1;
            q0.x = __float2bfloat16(s0 * inv); q0.y = __float2bfloat16(s1 * inv);
            q1.x = __float2bfloat16(s2 * inv); q1.y = __float2bfloat16(s3 * inv);
            uint2 st;
            st.x = *reinterpret_cast<uint32_t*>(&q0);
            st.y = *reinterpret_cast<uint32_t*>(&q1);
            *reinterpret_cast<uint2*>(&As[row * AP + kq]) = st;
        }
        __syncthreads();
        mma_chunk(As_u32, Bs_u32, kc, wm, wn, lane, acc);
    }

#pragma unroll
    for (int mi = 0; mi < 2; mi++) {
        int rb = row0 + wm * 32 + mi * 16;
#pragma unroll
        for (int half = 0; half < 2; half++) {
            int r = rb + qr + half * 8;
            float* dst = out + (size_t)r * EMBED;
            const float* qsrc = query + (size_t)r * EMBED;
#pragma unroll
            for (int ni = 0; ni < 8; ni++) {
                int n = n0 + wn * 64 + ni * 8 + qc * 2;
                float2 qv = *reinterpret_cast<const float2*>(qsrc + n);
                float2 o;
                o.x = acc[mi][ni][half * 2 + 0] + bout[n] + qv.x;
                o.y = acc[mi][ni][half * 2 + 1] + bout[n + 1] + qv.y;
                *reinterpret_cast<float2*>(dst + n) = o;
            }
        }
    }
}

// =======================================================================
extern "C" void kernel_launch(void* const* d_in, const int* in_sizes, int n_in,
                              void* d_out, int out_size)
{
    const float* query = (const float*)d_in[0];
    /* d_in[1] = key : unused by the reference */
    const float* value = (const float*)d_in[2];
    const float* qpos  = (const float*)d_in[3];
    const float* refc  = (const float*)d_in[4];
    const unsigned int* bmask = (const unsigned int*)d_in[5];
    /* d_in[6] spatial_shapes, d_in[7] level_start_index : compile-time constants */
    const float* Wv   = (const float*)d_in[8];
    const float* bv   = (const float*)d_in[9];
    const float* Wso  = (const float*)d_in[10];
    const float* bso  = (const float*)d_in[11];
    const float* Waw  = (const float*)d_in[12];
    const float* baw  = (const float*)d_in[13];
    const float* Wout = (const float*)d_in[14];
    const float* bout = (const float*)d_in[15];
    float* out = (float*)d_out;

    cudaFuncSetAttribute(vproj_mma_kernel,
                         cudaFuncAttributeMaxDynamicSharedMemorySize, VP_SMEM);
    cudaFuncSetAttribute(offaw_mma_kernel,
                         cudaFuncAttributeMaxDynamicSharedMemorySize, VP_SMEM);
    cudaFuncSetAttribute(final_mma_kernel,
                         cudaFuncAttributeMaxDynamicSharedMemorySize, VP_SMEM);

    vproj_mma_kernel<<<dim3(2, PGRID), 256, VP_SMEM>>>(value, Wv, bv);
    offaw_mma_kernel<<<dim3(6, 25), 256, VP_SMEM>>>(query, qpos, Wso, bso, Waw, baw);
    mask_kernel     <<<25, 256>>>(bmask);
    sampler_kernel  <<<CAMS * NQ, 256>>>(refc);
    final_mma_kernel<<<dim3(2, 50), 256, VP_SMEM>>>(query, Wout, bout, out);
}

// round 10
// speedup vs baseline: 1.6557x; 1.6557x over previous
#include <cuda_runtime.h>
#include <cuda_bf16.h>
#include <cstdint>
#include <stdint.h>
#include <math.h>

#define CAMS   6
#define NQ     6400
#define EMBED  256
#define HEADS  8
#define LEVELS 4
#define POINTS 8
#define DEPTH  4
#define DH     32
#define FLEN   14960
#define MROWS  (CAMS * FLEN)   /* 89760 */
#define NOFFAW 768             /* 512 offsets + 256 aw logits */
#define NTILES 702             /* row tiles of 128 for vproj */
#define PGRID  176             /* persistent CTAs per column half */

// ---------------- static device scratch (no allocations allowed) ----------------
__device__ __nv_bfloat16 g_vproj [(size_t)MROWS * EMBED];      // ~46 MB  [c][f][256]
__device__ float         g_offaw [(size_t)NQ * NOFFAW];        // ~20 MB  [n][768]
__device__ __nv_bfloat16 g_outcam[(size_t)CAMS * NQ * EMBED];  // ~20 MB  [c][n][256]
__device__ int   g_maskq [CAMS * NQ];
__device__ float g_invcnt[NQ];

// ======================== shared mma tile machinery =====================
#define BP 264                 /* Bs pitch in bf16 (256 + 8) */
#define AP 40                  /* As pitch in bf16 (32 + 8)  */
#define GM_SMEM (128 * BP * 2 + 128 * AP * 2)       /* 77824 B (offaw/final) */
#define VP_SMEM (128 * BP * 2 + 2 * 128 * AP * 2)   /* 88064 B (vproj, dbuf A) */

__device__ __forceinline__ void mma_bf16(float* c, const uint32_t* a, const uint32_t* b)
{
    asm volatile(
        "mma.sync.aligned.m16n8k16.row.col.f32.bf16.bf16.f32 "
        "{%0,%1,%2,%3}, {%4,%5,%6,%7}, {%8,%9}, {%0,%1,%2,%3};"
        : "+f"(c[0]), "+f"(c[1]), "+f"(c[2]), "+f"(c[3])
        : "r"(a[0]), "r"(a[1]), "r"(a[2]), "r"(a[3]), "r"(b[0]), "r"(b[1]));
}

// inner-loop body shared by all three GEMMs (scalar LDS version — R7 proven)
__device__ __forceinline__ void mma_chunk(
    const __nv_bfloat16* As, const __nv_bfloat16* Bs, int kc,
    int wm, int wn, int qr, int qc, float acc[2][8][4])
{
#pragma unroll
    for (int ks = 0; ks < 32; ks += 16) {
        uint32_t a[2][4], b[8][2];
#pragma unroll
        for (int mi = 0; mi < 2; mi++) {
            int rb = wm * 32 + mi * 16;
            a[mi][0] = *reinterpret_cast<const uint32_t*>(&As[(rb + qr)     * AP + ks + qc * 2]);
            a[mi][1] = *reinterpret_cast<const uint32_t*>(&As[(rb + qr + 8) * AP + ks + qc * 2]);
            a[mi][2] = *reinterpret_cast<const uint32_t*>(&As[(rb + qr)     * AP + ks + qc * 2 + 8]);
            a[mi][3] = *reinterpret_cast<const uint32_t*>(&As[(rb + qr + 8) * AP + ks + qc * 2 + 8]);
        }
#pragma unroll
        for (int ni = 0; ni < 8; ni++) {
            int nn = wn * 64 + ni * 8 + qr;
            b[ni][0] = *reinterpret_cast<const uint32_t*>(&Bs[nn * BP + kc * 32 + ks + qc * 2]);
            b[ni][1] = *reinterpret_cast<const uint32_t*>(&Bs[nn * BP + kc * 32 + ks + qc * 2 + 8]);
        }
#pragma unroll
        for (int mi = 0; mi < 2; mi++)
#pragma unroll
            for (int ni = 0; ni < 8; ni++)
                mma_bf16(acc[mi][ni], a[mi], b[ni]);
    }
}

// =======================================================================
// GEMM 1: vproj[r][n] = value_row(r) @ Wv[:, n] + bv[n]  (bf16 out)
// Double-buffered A staging: ONE __syncthreads per k-chunk.
// =======================================================================
__global__ __launch_bounds__(256) void vproj_mma_kernel(
    const float* __restrict__ value, const float* __restrict__ Wv,
    const float* __restrict__ bv)
{
    extern __shared__ char smem[];
    __nv_bfloat16* Bs  = reinterpret_cast<__nv_bfloat16*>(smem);
    __nv_bfloat16* As0 = reinterpret_cast<__nv_bfloat16*>(smem + 128 * BP * 2);
    __nv_bfloat16* As1 = As0 + 128 * AP;

    const int tid  = threadIdx.x;
    const int wid  = tid >> 5;
    const int lane = tid & 31;
    const int wm   = wid >> 1;
    const int wn   = wid & 1;
    const int n0   = blockIdx.x * 128;
    const int row0 = blockIdx.y * 128;
    const int qr = lane >> 2, qc = lane & 3;

    // ---- B fill ----
#pragma unroll
    for (int i = 0; i < 64; i++) {
        int u  = i * 256 + tid;
        int k  = u >> 6;
        int np = u & 63;
        float2 w = *reinterpret_cast<const float2*>(Wv + (size_t)k * EMBED + n0 + np * 2);
        Bs[(np * 2 + 0) * BP + k] = __float2bfloat16(w.x);
        Bs[(np * 2 + 1) * BP + k] = __float2bfloat16(w.y);
    }

    const float* aptr[4];
    int arows[4], akq[4];
#pragma unroll
    for (int i = 0; i < 4; i++) {
        int u   = i * 256 + tid;
        arows[i] = u >> 3;
        akq[i]  = (u & 7) * 4;
        int r = row0 + arows[i];
        if (r >= MROWS) r = MROWS - 1;
        int c = r / FLEN;
        int f = r - c * FLEN;
        aptr[i] = value + ((size_t)f * CAMS + c) * EMBED + akq[i];
    }

    float acc[2][8][4];
#pragma unroll
    for (int mi = 0; mi < 2; mi++)
#pragma unroll
        for (int ni = 0; ni < 8; ni++)
#pragma unroll
            for (int j = 0; j < 4; j++) acc[mi][ni][j] = 0.f;

    float4 v[4];
#pragma unroll
    for (int i = 0; i < 4; i++) v[i] = *reinterpret_cast<const float4*>(aptr[i]);

    __syncthreads();   // B ready

    for (int kc = 0; kc < 8; kc++) {
        __nv_bfloat16* As = (kc & 1) ? As1 : As0;
#pragma unroll
        for (int i = 0; i < 4; i++) {
            __nv_bfloat162 p0, p1;
            p0.x = __float2bfloat16(v[i].x); p0.y = __float2bfloat16(v[i].y);
            p1.x = __float2bfloat16(v[i].z); p1.y = __float2bfloat16(v[i].w);
            uint2 st;
            st.x = *reinterpret_cast<uint32_t*>(&p0);
            st.y = *reinterpret_cast<uint32_t*>(&p1);
            *reinterpret_cast<uint2*>(&As[arows[i] * AP + akq[i]]) = st;
        }
        __syncthreads();
        if (kc < 7) {
#pragma unroll
            for (int i = 0; i < 4; i++)
                v[i] = *reinterpret_cast<const float4*>(aptr[i] + (kc + 1) * 32);
        }
        mma_chunk(As, Bs, kc, wm, wn, qr, qc, acc);
    }

#pragma unroll
    for (int mi = 0; mi < 2; mi++) {
        int rb = row0 + wm * 32 + mi * 16;
#pragma unroll
        for (int half = 0; half < 2; half++) {
            int r = rb + qr + half * 8;
            if (r >= MROWS) continue;
            __nv_bfloat16* dst = g_vproj + (size_t)r * EMBED;
#pragma unroll
            for (int ni = 0; ni < 8; ni++) {
                int n = n0 + wn * 64 + ni * 8 + qc * 2;
                __nv_bfloat162 o;
                o.x = __float2bfloat16(acc[mi][ni][half * 2 + 0] + bv[n]);
                o.y = __float2bfloat16(acc[mi][ni][half * 2 + 1] + bv[n + 1]);
                *reinterpret_cast<__nv_bfloat162*>(dst + n) = o;
            }
        }
    }
}

// =======================================================================
// GEMM 2: offaw[r][col] = (query+qpos)(r,:) @ [Wso|Waw](:,col) + bias
// =======================================================================
__global__ __launch_bounds__(256) void offaw_mma_kernel(
    const float* __restrict__ query, const float* __restrict__ qpos,
    const float* __restrict__ Wso, const float* __restrict__ bso,
    const float* __restrict__ Waw, const float* __restrict__ baw)
{
    extern __shared__ char smem[];
    __nv_bfloat16* Bs = reinterpret_cast<__nv_bfloat16*>(smem);
    __nv_bfloat16* As = reinterpret_cast<__nv_bfloat16*>(smem + 128 * BP * 2);

    const int tid  = threadIdx.x;
    const int wid  = tid >> 5;
    const int lane = tid & 31;
    const int wm   = wid >> 1;
    const int wn   = wid & 1;
    const int n0   = blockIdx.x * 128;        // 0..640
    const int row0 = blockIdx.y * 128;
    const int qr = lane >> 2, qc = lane & 3;

    const bool is_so   = (n0 < 512);
    const float* Bsrc  = is_so ? Wso : Waw;
    const int    bstr  = is_so ? 512 : 256;
    const int    bcol0 = is_so ? n0 : (n0 - 512);

#pragma unroll
    for (int i = 0; i < 64; i++) {
        int u  = i * 256 + tid;
        int k  = u >> 6;
        int np = u & 63;
        float2 w = *reinterpret_cast<const float2*>(Bsrc + (size_t)k * bstr + bcol0 + np * 2);
        Bs[(np * 2 + 0) * BP + k] = __float2bfloat16(w.x);
        Bs[(np * 2 + 1) * BP + k] = __float2bfloat16(w.y);
    }

    float acc[2][8][4];
#pragma unroll
    for (int mi = 0; mi < 2; mi++)
#pragma unroll
        for (int ni = 0; ni < 8; ni++)
#pragma unroll
            for (int j = 0; j < 4; j++) acc[mi][ni][j] = 0.f;

    for (int kc = 0; kc < 8; kc++) {
        __syncthreads();
#pragma unroll
        for (int i = 0; i < 4; i++) {
            int u   = i * 256 + tid;
            int row = u >> 3;
            int kq  = (u & 7) * 4;
            int r = row0 + row;
            float4 a = *reinterpret_cast<const float4*>(query + (size_t)r * EMBED + kc * 32 + kq);
            float4 p = *reinterpret_cast<const float4*>(qpos  + (size_t)r * EMBED + kc * 32 + kq);
            __nv_bfloat162 p0, p1;
            p0.x = __float2bfloat16(a.x + p.x); p0.y = __float2bfloat16(a.y + p.y);
            p1.x = __float2bfloat16(a.z + p.z); p1.y = __float2bfloat16(a.w + p.w);
            uint2 st;
            st.x = *reinterpret_cast<uint32_t*>(&p0);
            st.y = *reinterpret_cast<uint32_t*>(&p1);
            *reinterpret_cast<uint2*>(&As[row * AP + kq]) = st;
        }
        __syncthreads();
        mma_chunk(As, Bs, kc, wm, wn, qr, qc, acc);
    }

#pragma unroll
    for (int mi = 0; mi < 2; mi++) {
        int rb = row0 + wm * 32 + mi * 16;
#pragma unroll
        for (int half = 0; half < 2; half++) {
            int r = rb + qr + half * 8;
            float* dst = g_offaw + (size_t)r * NOFFAW;
#pragma unroll
            for (int ni = 0; ni < 8; ni++) {
                int col = n0 + wn * 64 + ni * 8 + qc * 2;
                float b0 = (col < 512) ? bso[col] : baw[col - 512];
                float b1 = (col + 1 < 512) ? bso[col + 1] : baw[col + 1 - 512];
                float2 o;
                o.x = acc[mi][ni][half * 2 + 0] + b0;
                o.y = acc[mi][ni][half * 2 + 1] + b1;
                *reinterpret_cast<float2*>(dst + col) = o;
            }
        }
    }
}

// =======================================================================
// mask / count
// =======================================================================
__global__ void mask_kernel(const unsigned int* __restrict__ bm)
{
    int n = blockIdx.x * blockDim.x + threadIdx.x;
    if (n >= NQ) return;
    int cnt = 0;
#pragma unroll
    for (int c = 0; c < CAMS; c++) {
        const unsigned int* q = bm + ((size_t)c * NQ + n) * DEPTH;
        unsigned int any = q[0] | q[1] | q[2] | q[3];
        int m = any ? 1 : 0;
        g_maskq[c * NQ + n] = m;
        cnt += m;
    }
    g_invcnt[n] = 1.0f / fmaxf((float)cnt, 1.0f);
}

// =======================================================================
// MSDA sampler, two-phase, softmax fused (quarter-warp gather) — R7 proven
// =======================================================================
__global__ __launch_bounds__(256) void sampler_kernel(const float* __restrict__ refcam)
{
    const int bx = blockIdx.x;           // c*NQ + n
    const int c  = bx / NQ;
    const int n  = bx - c * NQ;
    __shared__ float sref[8];
    __shared__ int   smask;
    __shared__ int4   sidx[256];
    __shared__ float4 swt [256];

    const int tid = threadIdx.x;
    if (tid == 0) smask = g_maskq[bx];
    if (tid < 8) sref[tid] = refcam[(size_t)bx * 8 + tid];
    __syncthreads();
    if (!smask) {
        g_outcam[(size_t)bx * EMBED + tid] = __float2bfloat16(0.f);
        return;
    }

    // ---- phase 1: softmax + coordinates & weights (warp == head) ----
    {
        const int s = tid & 31;          // sample within head
        const int l = s >> 3;
        const int d = s & 3;
        const int   cWl[4] = {176, 88, 44, 22};
        const int   cHl[4] = {64, 32, 16, 8};
        const int   cls[4] = {0, 11264, 14080, 14784};
        const int Wl = cWl[l], Hl = cHl[l], ls = cls[l];

        float2 off   = *reinterpret_cast<const float2*>(g_offaw + (size_t)n * NOFFAW + 2 * tid);
        float  logit = g_offaw[(size_t)n * NOFFAW + 512 + tid];

        float m = logit;
#pragma unroll
        for (int o = 16; o; o >>= 1) m = fmaxf(m, __shfl_xor_sync(0xffffffffu, m, o));
        float e = __expf(logit - m);
        float ssum = e;
#pragma unroll
        for (int o = 16; o; o >>= 1) ssum += __shfl_xor_sync(0xffffffffu, ssum, o);
        float aw = e / ssum;

        float x = sref[d * 2 + 0] * (float)Wl + off.x - 0.5f;
        float y = sref[d * 2 + 1] * (float)Hl + off.y - 0.5f;
        float x0f = floorf(x), y0f = floorf(y);
        float fx = x - x0f, fy = y - y0f;
        int x0 = (int)x0f, y0 = (int)y0f;
        int x1 = x0 + 1,   y1 = y0 + 1;

        float vx0 = ((unsigned)x0 < (unsigned)Wl) ? 1.f : 0.f;
        float vx1 = ((unsigned)x1 < (unsigned)Wl) ? 1.f : 0.f;
        float vy0 = ((unsigned)y0 < (unsigned)Hl) ? 1.f : 0.f;
        float vy1 = ((unsigned)y1 < (unsigned)Hl) ? 1.f : 0.f;

        int cx0 = min(max(x0, 0), Wl - 1);
        int cx1 = min(max(x1, 0), Wl - 1);
        int cy0 = min(max(y0, 0), Hl - 1);
        int cy1 = min(max(y1, 0), Hl - 1);

        int4 id;
        id.x = ls + cy0 * Wl + cx0;
        id.y = ls + cy0 * Wl + cx1;
        id.z = ls + cy1 * Wl + cx0;
        id.w = ls + cy1 * Wl + cx1;
        float4 w;
        w.x = (1.f - fx) * (1.f - fy) * aw * vx0 * vy0;
        w.y = fx * (1.f - fy) * aw * vx1 * vy0;
        w.z = (1.f - fx) * fy * aw * vx0 * vy1;
        w.w = fx * fy * aw * vx1 * vy1;
        sidx[tid] = id;
        swt [tid] = w;
    }
    __syncthreads();

    // ---- phase 2: quarter-warp vectorized gather ----
    {
        const int h    = tid >> 5;
        const int lane = tid & 31;
        const int g    = lane >> 3;      // group 0..3: sample s = it*4 + g
        const int j    = lane & 7;       // channel quad
        const uint16_t* vb = reinterpret_cast<const uint16_t*>(
            g_vproj + (size_t)c * FLEN * EMBED + h * DH + j * 4);
        float a0 = 0.f, a1 = 0.f, a2 = 0.f, a3 = 0.f;
#pragma unroll 2
        for (int it = 0; it < 8; it++) {
            int s = it * 4 + g;
            int4   id = sidx[h * 32 + s];
            float4 w  = swt [h * 32 + s];
            uint2 r0 = *reinterpret_cast<const uint2*>(vb + (size_t)id.x * EMBED);
            uint2 r1 = *reinterpret_cast<const uint2*>(vb + (size_t)id.y * EMBED);
            uint2 r2 = *reinterpret_cast<const uint2*>(vb + (size_t)id.z * EMBED);
            uint2 r3 = *reinterpret_cast<const uint2*>(vb + (size_t)id.w * EMBED);
            __nv_bfloat162 p;
            p = *reinterpret_cast<__nv_bfloat162*>(&r0.x);
            a0 = fmaf(w.x, __bfloat162float(p.x), a0); a1 = fmaf(w.x, __bfloat162float(p.y), a1);
            p = *reinterpret_cast<__nv_bfloat162*>(&r0.y);
            a2 = fmaf(w.x, __bfloat162float(p.x), a2); a3 = fmaf(w.x, __bfloat162float(p.y), a3);
            p = *reinterpret_cast<__nv_bfloat162*>(&r1.x);
            a0 = fmaf(w.y, __bfloat162float(p.x), a0); a1 = fmaf(w.y, __bfloat162float(p.y), a1);
            p = *reinterpret_cast<__nv_bfloat162*>(&r1.y);
            a2 = fmaf(w.y, __bfloat162float(p.x), a2); a3 = fmaf(w.y, __bfloat162float(p.y), a3);
            p = *reinterpret_cast<__nv_bfloat162*>(&r2.x);
            a0 = fmaf(w.z, __bfloat162float(p.x), a0); a1 = fmaf(w.z, __bfloat162float(p.y), a1);
            p = *reinterpret_cast<__nv_bfloat162*>(&r2.y);
            a2 = fmaf(w.z, __bfloat162float(p.x), a2); a3 = fmaf(w.z, __bfloat162float(p.y), a3);
            p = *reinterpret_cast<__nv_bfloat162*>(&r3.x);
            a0 = fmaf(w.w, __bfloat162float(p.x), a0); a1 = fmaf(w.w, __bfloat162float(p.y), a1);
            p = *reinterpret_cast<__nv_bfloat162*>(&r3.y);
            a2 = fmaf(w.w, __bfloat162float(p.x), a2); a3 = fmaf(w.w, __bfloat162float(p.y), a3);
        }
        a0 += __shfl_xor_sync(0xffffffffu, a0, 8);
        a1 += __shfl_xor_sync(0xffffffffu, a1, 8);
        a2 += __shfl_xor_sync(0xffffffffu, a2, 8);
        a3 += __shfl_xor_sync(0xffffffffu, a3, 8);
        a0 += __shfl_xor_sync(0xffffffffu, a0, 16);
        a1 += __shfl_xor_sync(0xffffffffu, a1, 16);
        a2 += __shfl_xor_sync(0xffffffffu, a2, 16);
        a3 += __shfl_xor_sync(0xffffffffu, a3, 16);
        if (g == 0) {
            __nv_bfloat162 o0, o1;
            o0.x = __float2bfloat16(a0); o0.y = __float2bfloat16(a1);
            o1.x = __float2bfloat16(a2); o1.y = __float2bfloat16(a3);
            uint2 st;
            st.x = *reinterpret_cast<uint32_t*>(&o0);
            st.y = *reinterpret_cast<uint32_t*>(&o1);
            *reinterpret_cast<uint2*>(
                g_outcam + (size_t)bx * EMBED + h * DH + j * 4) = st;
        }
    }
}

// =======================================================================
// GEMM 3 (final mma): A[r][k] = invcnt[r]*sum_c outcam[c][r][k] (bf16)
// out = A @ Wout + bout + query.  M=6400, N=256, K=256.
// =======================================================================
__global__ __launch_bounds__(256) void final_mma_kernel(
    const float* __restrict__ query, const float* __restrict__ Wout,
    const float* __restrict__ bout, float* __restrict__ out)
{
    extern __shared__ char smem[];
    __nv_bfloat16* Bs = reinterpret_cast<__nv_bfloat16*>(smem);
    __nv_bfloat16* As = reinterpret_cast<__nv_bfloat16*>(smem + 128 * BP * 2);

    const int tid  = threadIdx.x;
    const int wid  = tid >> 5;
    const int lane = tid & 31;
    const int wm   = wid >> 1;
    const int wn   = wid & 1;
    const int n0   = blockIdx.x * 128;
    const int row0 = blockIdx.y * 128;
    const int qr = lane >> 2, qc = lane & 3;

#pragma unroll
    for (int i = 0; i < 64; i++) {
        int u  = i * 256 + tid;
        int k  = u >> 6;
        int np = u & 63;
        float2 w = *reinterpret_cast<const float2*>(Wout + (size_t)k * EMBED + n0 + np * 2);
        Bs[(np * 2 + 0) * BP + k] = __float2bfloat16(w.x);
        Bs[(np * 2 + 1) * BP + k] = __float2bfloat16(w.y);
    }

    float acc[2][8][4];
#pragma unroll
    for (int mi = 0; mi < 2; mi++)
#pragma unroll
        for (int ni = 0; ni < 8; ni++)
#pragma unroll
            for (int j = 0; j < 4; j++) acc[mi][ni][j] = 0.f;

    for (int kc = 0; kc < 8; kc++) {
        __syncthreads();
#pragma unroll
        for (int i = 0; i < 4; i++) {
            int u   = i * 256 + tid;
            int row = u >> 3;
            int kq  = (u & 7) * 4;
            int r = row0 + row;
            float inv = g_invcnt[r];
            float s0 = 0.f, s1 = 0.f, s2 = 0.f, s3 = 0.f;
#pragma unroll
            for (int c = 0; c < CAMS; c++) {
                const __nv_bfloat16* src =
                    g_outcam + ((size_t)c * NQ + r) * EMBED + kc * 32 + kq;
                uint2 u2 = *reinterpret_cast<const uint2*>(src);
                __nv_bfloat162 p0 = *reinterpret_cast<__nv_bfloat162*>(&u2.x);
                __nv_bfloat162 p1 = *reinterpret_cast<__nv_bfloat162*>(&u2.y);
                s0 += __bfloat162float(p0.x); s1 += __bfloat162float(p0.y);
                s2 += __bfloat162float(p1.x); s3 += __bfloat162float(p1.y);
            }
            __nv_bfloat162 q0, q1;
            q0.x = __float2bfloat16(s0 * inv); q0.y = __float2bfloat16(s1 * inv);
            q1.x = __float2bfloat16(s2 * inv); q1.y = __float2bfloat16(s3 * inv);
            uint2 st;
            st.x = *reinterpret_cast<uint32_t*>(&q0);
            st.y = *reinterpret_cast<uint32_t*>(&q1);
            *reinterpret_cast<uint2*>(&As[row * AP + kq]) = st;
        }
        __syncthreads();
        mma_chunk(As, Bs, kc, wm, wn, qr, qc, acc);
    }

#pragma unroll
    for (int mi = 0; mi < 2; mi++) {
        int rb = row0 + wm * 32 + mi * 16;
#pragma unroll
        for (int half = 0; half < 2; half++) {
            int r = rb + qr + half * 8;
            float* dst = out + (size_t)r * EMBED;
            const float* qsrc = query + (size_t)r * EMBED;
#pragma unroll
            for (int ni = 0; ni < 8; ni++) {
                int n = n0 + wn * 64 + ni * 8 + qc * 2;
                float2 qv = *reinterpret_cast<const float2*>(qsrc + n);
                float2 o;
                o.x = acc[mi][ni][half * 2 + 0] + bout[n] + qv.x;
                o.y = acc[mi][ni][half * 2 + 1] + bout[n + 1] + qv.y;
                *reinterpret_cast<float2*>(dst + n) = o;
            }
        }
    }
}

// =======================================================================
extern "C" void kernel_launch(void* const* d_in, const int* in_sizes, int n_in,
                              void* d_out, int out_size)
{
    const float* query = (const float*)d_in[0];
    /* d_in[1] = key : unused by the reference */
    const float* value = (const float*)d_in[2];
    const float* qpos  = (const float*)d_in[3];
    const float* refc  = (const float*)d_in[4];
    const unsigned int* bmask = (const unsigned int*)d_in[5];
    /* d_in[6] spatial_shapes, d_in[7] level_start_index : compile-time constants */
    const float* Wv   = (const float*)d_in[8];
    const float* bv   = (const float*)d_in[9];
    const float* Wso  = (const float*)d_in[10];
    const float* bso  = (const float*)d_in[11];
    const float* Waw  = (const float*)d_in[12];
    const float* baw  = (const float*)d_in[13];
    const float* Wout = (const float*)d_in[14];
    const float* bout = (const float*)d_in[15];
    float* out = (float*)d_out;

    cudaFuncSetAttribute(vproj_mma_kernel,
                         cudaFuncAttributeMaxDynamicSharedMemorySize, VP_SMEM);
    cudaFuncSetAttribute(offaw_mma_kernel,
                         cudaFuncAttributeMaxDynamicSharedMemorySize, GM_SMEM);
    cudaFuncSetAttribute(final_mma_kernel,
                         cudaFuncAttributeMaxDynamicSharedMemorySize, GM_SMEM);

    vproj_mma_kernel<<<dim3(2, 702), 256, VP_SMEM>>>(value, Wv, bv);
    offaw_mma_kernel<<<dim3(6, 50), 256, GM_SMEM>>>(query, qpos, Wso, bso, Waw, baw);
    mask_kernel     <<<25, 256>>>(bmask);
    sampler_kernel  <<<CAMS * NQ, 256>>>(refc);
    final_mma_kernel<<<dim3(2, 50), 256, GM_SMEM>>>(query, Wout, bout, out);
}

// round 11
// speedup vs baseline: 1.7572x; 1.0613x over previous
#include <cuda_runtime.h>
#include <cuda_bf16.h>
#include <cstdint>
#include <stdint.h>
#include <math.h>

#define CAMS   6
#define NQ     6400
#define EMBED  256
#define HEADS  8
#define LEVELS 4
#define POINTS 8
#define DEPTH  4
#define DH     32
#define FLEN   14960
#define MROWS  (CAMS * FLEN)   /* 89760 */
#define NOFFAW 768             /* 512 offsets + 256 aw logits */

/* stage1 fused grid layout */
#define VP_BLOCKS    1404      /* 2 column halves x 702 row tiles */
#define OFFAW_START  1404
#define OFFAW_BLOCKS 300       /* 6 col tiles x 50 row tiles */
#define MASK_START   1704
#define MASK_BLOCKS  25
#define S1_BLOCKS    1729

// ---------------- static device scratch (no allocations allowed) ----------------
__device__ __nv_bfloat16 g_vproj [(size_t)MROWS * EMBED];      // ~46 MB  [c][f][256]
__device__ float         g_offaw [(size_t)NQ * NOFFAW];        // ~20 MB  [n][768]
__device__ __nv_bfloat16 g_outcam[(size_t)CAMS * NQ * EMBED];  // ~20 MB  [c][n][256]
__device__ int   g_maskq [CAMS * NQ];
__device__ float g_invcnt[NQ];

// ======================== shared mma tile machinery =====================
#define BP 264                 /* Bs pitch in bf16 (256 + 8) */
#define AP 40                  /* As pitch in bf16 (32 + 8)  */
#define GM_SMEM (128 * BP * 2 + 128 * AP * 2)       /* 77824 B (offaw/final) */
#define VP_SMEM (128 * BP * 2 + 2 * 128 * AP * 2)   /* 88064 B (stage1)      */

__device__ __forceinline__ void mma_bf16(float* c, const uint32_t* a, const uint32_t* b)
{
    asm volatile(
        "mma.sync.aligned.m16n8k16.row.col.f32.bf16.bf16.f32 "
        "{%0,%1,%2,%3}, {%4,%5,%6,%7}, {%8,%9}, {%0,%1,%2,%3};"
        : "+f"(c[0]), "+f"(c[1]), "+f"(c[2]), "+f"(c[3])
        : "r"(a[0]), "r"(a[1]), "r"(a[2]), "r"(a[3]), "r"(b[0]), "r"(b[1]));
}

// inner-loop body shared by all GEMMs (scalar LDS version — proven)
__device__ __forceinline__ void mma_chunk(
    const __nv_bfloat16* As, const __nv_bfloat16* Bs, int kc,
    int wm, int wn, int qr, int qc, float acc[2][8][4])
{
#pragma unroll
    for (int ks = 0; ks < 32; ks += 16) {
        uint32_t a[2][4], b[8][2];
#pragma unroll
        for (int mi = 0; mi < 2; mi++) {
            int rb = wm * 32 + mi * 16;
            a[mi][0] = *reinterpret_cast<const uint32_t*>(&As[(rb + qr)     * AP + ks + qc * 2]);
            a[mi][1] = *reinterpret_cast<const uint32_t*>(&As[(rb + qr + 8) * AP + ks + qc * 2]);
            a[mi][2] = *reinterpret_cast<const uint32_t*>(&As[(rb + qr)     * AP + ks + qc * 2 + 8]);
            a[mi][3] = *reinterpret_cast<const uint32_t*>(&As[(rb + qr + 8) * AP + ks + qc * 2 + 8]);
        }
#pragma unroll
        for (int ni = 0; ni < 8; ni++) {
            int nn = wn * 64 + ni * 8 + qr;
            b[ni][0] = *reinterpret_cast<const uint32_t*>(&Bs[nn * BP + kc * 32 + ks + qc * 2]);
            b[ni][1] = *reinterpret_cast<const uint32_t*>(&Bs[nn * BP + kc * 32 + ks + qc * 2 + 8]);
        }
#pragma unroll
        for (int mi = 0; mi < 2; mi++)
#pragma unroll
            for (int ni = 0; ni < 8; ni++)
                mma_bf16(acc[mi][ni], a[mi], b[ni]);
    }
}

// =======================================================================
// STAGE 1 (fused): vproj GEMM + offaw GEMM + mask — independent work,
// partitioned by blockIdx.x so offaw/mask backfill vproj's tail waves.
// =======================================================================
__global__ __launch_bounds__(256) void stage1_kernel(
    const float* __restrict__ value, const float* __restrict__ Wv,
    const float* __restrict__ bv,
    const float* __restrict__ query, const float* __restrict__ qpos,
    const float* __restrict__ Wso, const float* __restrict__ bso,
    const float* __restrict__ Waw, const float* __restrict__ baw,
    const unsigned int* __restrict__ bmask)
{
    extern __shared__ char smem[];
    const int bx  = blockIdx.x;
    const int tid = threadIdx.x;

    // ------------------------- mask part -------------------------
    if (bx >= MASK_START) {
        int n = (bx - MASK_START) * 256 + tid;
        if (n < NQ) {
            int cnt = 0;
#pragma unroll
            for (int c = 0; c < CAMS; c++) {
                const unsigned int* q = bmask + ((size_t)c * NQ + n) * DEPTH;
                unsigned int any = q[0] | q[1] | q[2] | q[3];
                int m = any ? 1 : 0;
                g_maskq[c * NQ + n] = m;
                cnt += m;
            }
            g_invcnt[n] = 1.0f / fmaxf((float)cnt, 1.0f);
        }
        return;
    }

    const int wid  = tid >> 5;
    const int lane = tid & 31;
    const int wm   = wid >> 1;
    const int wn   = wid & 1;
    const int qr   = lane >> 2, qc = lane & 3;

    // ------------------------- offaw part -------------------------
    if (bx >= OFFAW_START) {
        __nv_bfloat16* Bs = reinterpret_cast<__nv_bfloat16*>(smem);
        __nv_bfloat16* As = reinterpret_cast<__nv_bfloat16*>(smem + 128 * BP * 2);
        const int bid  = bx - OFFAW_START;
        const int n0   = (bid % 6) * 128;
        const int row0 = (bid / 6) * 128;

        const bool is_so   = (n0 < 512);
        const float* Bsrc  = is_so ? Wso : Waw;
        const int    bstr  = is_so ? 512 : 256;
        const int    bcol0 = is_so ? n0 : (n0 - 512);

#pragma unroll
        for (int i = 0; i < 64; i++) {
            int u  = i * 256 + tid;
            int k  = u >> 6;
            int np = u & 63;
            float2 w = *reinterpret_cast<const float2*>(Bsrc + (size_t)k * bstr + bcol0 + np * 2);
            Bs[(np * 2 + 0) * BP + k] = __float2bfloat16(w.x);
            Bs[(np * 2 + 1) * BP + k] = __float2bfloat16(w.y);
        }

        float acc[2][8][4];
#pragma unroll
        for (int mi = 0; mi < 2; mi++)
#pragma unroll
            for (int ni = 0; ni < 8; ni++)
#pragma unroll
                for (int j = 0; j < 4; j++) acc[mi][ni][j] = 0.f;

        for (int kc = 0; kc < 8; kc++) {
            __syncthreads();
#pragma unroll
            for (int i = 0; i < 4; i++) {
                int u   = i * 256 + tid;
                int row = u >> 3;
                int kq  = (u & 7) * 4;
                int r = row0 + row;
                float4 a = *reinterpret_cast<const float4*>(query + (size_t)r * EMBED + kc * 32 + kq);
                float4 p = *reinterpret_cast<const float4*>(qpos  + (size_t)r * EMBED + kc * 32 + kq);
                __nv_bfloat162 p0, p1;
                p0.x = __float2bfloat16(a.x + p.x); p0.y = __float2bfloat16(a.y + p.y);
                p1.x = __float2bfloat16(a.z + p.z); p1.y = __float2bfloat16(a.w + p.w);
                uint2 st;
                st.x = *reinterpret_cast<uint32_t*>(&p0);
                st.y = *reinterpret_cast<uint32_t*>(&p1);
                *reinterpret_cast<uint2*>(&As[row * AP + kq]) = st;
            }
            __syncthreads();
            mma_chunk(As, Bs, kc, wm, wn, qr, qc, acc);
        }

#pragma unroll
        for (int mi = 0; mi < 2; mi++) {
            int rb = row0 + wm * 32 + mi * 16;
#pragma unroll
            for (int half = 0; half < 2; half++) {
                int r = rb + qr + half * 8;
                float* dst = g_offaw + (size_t)r * NOFFAW;
#pragma unroll
                for (int ni = 0; ni < 8; ni++) {
                    int col = n0 + wn * 64 + ni * 8 + qc * 2;
                    float b0 = (col < 512) ? bso[col] : baw[col - 512];
                    float b1 = (col + 1 < 512) ? bso[col + 1] : baw[col + 1 - 512];
                    float2 o;
                    o.x = acc[mi][ni][half * 2 + 0] + b0;
                    o.y = acc[mi][ni][half * 2 + 1] + b1;
                    *reinterpret_cast<float2*>(dst + col) = o;
                }
            }
        }
        return;
    }

    // ------------------------- vproj part -------------------------
    {
        __nv_bfloat16* Bs  = reinterpret_cast<__nv_bfloat16*>(smem);
        __nv_bfloat16* As0 = reinterpret_cast<__nv_bfloat16*>(smem + 128 * BP * 2);
        __nv_bfloat16* As1 = As0 + 128 * AP;
        const int n0   = (bx & 1) * 128;
        const int row0 = (bx >> 1) * 128;

        // ---- B fill ----
#pragma unroll
        for (int i = 0; i < 64; i++) {
            int u  = i * 256 + tid;
            int k  = u >> 6;
            int np = u & 63;
            float2 w = *reinterpret_cast<const float2*>(Wv + (size_t)k * EMBED + n0 + np * 2);
            Bs[(np * 2 + 0) * BP + k] = __float2bfloat16(w.x);
            Bs[(np * 2 + 1) * BP + k] = __float2bfloat16(w.y);
        }

        const float* aptr[4];
        int arows[4], akq[4];
#pragma unroll
        for (int i = 0; i < 4; i++) {
            int u   = i * 256 + tid;
            arows[i] = u >> 3;
            akq[i]  = (u & 7) * 4;
            int r = row0 + arows[i];
            if (r >= MROWS) r = MROWS - 1;
            int c = r / FLEN;
            int f = r - c * FLEN;
            aptr[i] = value + ((size_t)f * CAMS + c) * EMBED + akq[i];
        }

        float acc[2][8][4];
#pragma unroll
        for (int mi = 0; mi < 2; mi++)
#pragma unroll
            for (int ni = 0; ni < 8; ni++)
#pragma unroll
                for (int j = 0; j < 4; j++) acc[mi][ni][j] = 0.f;

        float4 v[4];
#pragma unroll
        for (int i = 0; i < 4; i++) v[i] = *reinterpret_cast<const float4*>(aptr[i]);

        __syncthreads();   // B ready

        for (int kc = 0; kc < 8; kc++) {
            __nv_bfloat16* As = (kc & 1) ? As1 : As0;
#pragma unroll
            for (int i = 0; i < 4; i++) {
                __nv_bfloat162 p0, p1;
                p0.x = __float2bfloat16(v[i].x); p0.y = __float2bfloat16(v[i].y);
                p1.x = __float2bfloat16(v[i].z); p1.y = __float2bfloat16(v[i].w);
                uint2 st;
                st.x = *reinterpret_cast<uint32_t*>(&p0);
                st.y = *reinterpret_cast<uint32_t*>(&p1);
                *reinterpret_cast<uint2*>(&As[arows[i] * AP + akq[i]]) = st;
            }
            __syncthreads();
            if (kc < 7) {
#pragma unroll
                for (int i = 0; i < 4; i++)
                    v[i] = *reinterpret_cast<const float4*>(aptr[i] + (kc + 1) * 32);
            }
            mma_chunk(As, Bs, kc, wm, wn, qr, qc, acc);
        }

#pragma unroll
        for (int mi = 0; mi < 2; mi++) {
            int rb = row0 + wm * 32 + mi * 16;
#pragma unroll
            for (int half = 0; half < 2; half++) {
                int r = rb + qr + half * 8;
                if (r >= MROWS) continue;
                __nv_bfloat16* dst = g_vproj + (size_t)r * EMBED;
#pragma unroll
                for (int ni = 0; ni < 8; ni++) {
                    int n = n0 + wn * 64 + ni * 8 + qc * 2;
                    __nv_bfloat162 o;
                    o.x = __float2bfloat16(acc[mi][ni][half * 2 + 0] + bv[n]);
                    o.y = __float2bfloat16(acc[mi][ni][half * 2 + 1] + bv[n + 1]);
                    *reinterpret_cast<__nv_bfloat162*>(dst + n) = o;
                }
            }
        }
    }
}

// =======================================================================
// MSDA sampler, two-phase, softmax fused (quarter-warp gather)
// =======================================================================
__global__ __launch_bounds__(256) void sampler_kernel(const float* __restrict__ refcam)
{
    const int bx = blockIdx.x;           // c*NQ + n
    const int c  = bx / NQ;
    const int n  = bx - c * NQ;
    __shared__ float sref[8];
    __shared__ int4   sidx[256];
    __shared__ float4 swt [256];

    const int tid = threadIdx.x;
    if (!g_maskq[bx]) {                  // uniform broadcast load
        g_outcam[(size_t)bx * EMBED + tid] = __float2bfloat16(0.f);
        return;
    }
    if (tid < 8) sref[tid] = refcam[(size_t)bx * 8 + tid];
    __syncthreads();

    // ---- phase 1: softmax + coordinates & weights (warp == head) ----
    {
        const int s = tid & 31;          // sample within head
        const int l = s >> 3;
        const int d = s & 3;
        const int   cWl[4] = {176, 88, 44, 22};
        const int   cHl[4] = {64, 32, 16, 8};
        const int   cls[4] = {0, 11264, 14080, 14784};
        const int Wl = cWl[l], Hl = cHl[l], ls = cls[l];

        float2 off   = *reinterpret_cast<const float2*>(g_offaw + (size_t)n * NOFFAW + 2 * tid);
        float  logit = g_offaw[(size_t)n * NOFFAW + 512 + tid];

        float m = logit;
#pragma unroll
        for (int o = 16; o; o >>= 1) m = fmaxf(m, __shfl_xor_sync(0xffffffffu, m, o));
        float e = __expf(logit - m);
        float ssum = e;
#pragma unroll
        for (int o = 16; o; o >>= 1) ssum += __shfl_xor_sync(0xffffffffu, ssum, o);
        float aw = e / ssum;

        float x = sref[d * 2 + 0] * (float)Wl + off.x - 0.5f;
        float y = sref[d * 2 + 1] * (float)Hl + off.y - 0.5f;
        float x0f = floorf(x), y0f = floorf(y);
        float fx = x - x0f, fy = y - y0f;
        int x0 = (int)x0f, y0 = (int)y0f;
        int x1 = x0 + 1,   y1 = y0 + 1;

        float vx0 = ((unsigned)x0 < (unsigned)Wl) ? 1.f : 0.f;
        float vx1 = ((unsigned)x1 < (unsigned)Wl) ? 1.f : 0.f;
        float vy0 = ((unsigned)y0 < (unsigned)Hl) ? 1.f : 0.f;
        float vy1 = ((unsigned)y1 < (unsigned)Hl) ? 1.f : 0.f;

        int cx0 = min(max(x0, 0), Wl - 1);
        int cx1 = min(max(x1, 0), Wl - 1);
        int cy0 = min(max(y0, 0), Hl - 1);
        int cy1 = min(max(y1, 0), Hl - 1);

        int4 id;
        id.x = ls + cy0 * Wl + cx0;
        id.y = ls + cy0 * Wl + cx1;
        id.z = ls + cy1 * Wl + cx0;
        id.w = ls + cy1 * Wl + cx1;
        float4 w;
        w.x = (1.f - fx) * (1.f - fy) * aw * vx0 * vy0;
        w.y = fx * (1.f - fy) * aw * vx1 * vy0;
        w.z = (1.f - fx) * fy * aw * vx0 * vy1;
        w.w = fx * fy * aw * vx1 * vy1;
        sidx[tid] = id;
        swt [tid] = w;
    }
    __syncthreads();

    // ---- phase 2: quarter-warp vectorized gather ----
    {
        const int h    = tid >> 5;
        const int lane = tid & 31;
        const int g    = lane >> 3;      // group 0..3: sample s = it*4 + g
        const int j    = lane & 7;       // channel quad
        const uint16_t* vb = reinterpret_cast<const uint16_t*>(
            g_vproj + (size_t)c * FLEN * EMBED + h * DH + j * 4);
        float a0 = 0.f, a1 = 0.f, a2 = 0.f, a3 = 0.f;
#pragma unroll 2
        for (int it = 0; it < 8; it++) {
            int s = it * 4 + g;
            int4   id = sidx[h * 32 + s];
            float4 w  = swt [h * 32 + s];
            uint2 r0 = *reinterpret_cast<const uint2*>(vb + (size_t)id.x * EMBED);
            uint2 r1 = *reinterpret_cast<const uint2*>(vb + (size_t)id.y * EMBED);
            uint2 r2 = *reinterpret_cast<const uint2*>(vb + (size_t)id.z * EMBED);
            uint2 r3 = *reinterpret_cast<const uint2*>(vb + (size_t)id.w * EMBED);
            __nv_bfloat162 p;
            p = *reinterpret_cast<__nv_bfloat162*>(&r0.x);
            a0 = fmaf(w.x, __bfloat162float(p.x), a0); a1 = fmaf(w.x, __bfloat162float(p.y), a1);
            p = *reinterpret_cast<__nv_bfloat162*>(&r0.y);
            a2 = fmaf(w.x, __bfloat162float(p.x), a2); a3 = fmaf(w.x, __bfloat162float(p.y), a3);
            p = *reinterpret_cast<__nv_bfloat162*>(&r1.x);
            a0 = fmaf(w.y, __bfloat162float(p.x), a0); a1 = fmaf(w.y, __bfloat162float(p.y), a1);
            p = *reinterpret_cast<__nv_bfloat162*>(&r1.y);
            a2 = fmaf(w.y, __bfloat162float(p.x), a2); a3 = fmaf(w.y, __bfloat162float(p.y), a3);
            p = *reinterpret_cast<__nv_bfloat162*>(&r2.x);
            a0 = fmaf(w.z, __bfloat162float(p.x), a0); a1 = fmaf(w.z, __bfloat162float(p.y), a1);
            p = *reinterpret_cast<__nv_bfloat162*>(&r2.y);
            a2 = fmaf(w.z, __bfloat162float(p.x), a2); a3 = fmaf(w.z, __bfloat162float(p.y), a3);
            p = *reinterpret_cast<__nv_bfloat162*>(&r3.x);
            a0 = fmaf(w.w, __bfloat162float(p.x), a0); a1 = fmaf(w.w, __bfloat162float(p.y), a1);
            p = *reinterpret_cast<__nv_bfloat162*>(&r3.y);
            a2 = fmaf(w.w, __bfloat162float(p.x), a2); a3 = fmaf(w.w, __bfloat162float(p.y), a3);
        }
        a0 += __shfl_xor_sync(0xffffffffu, a0, 8);
        a1 += __shfl_xor_sync(0xffffffffu, a1, 8);
        a2 += __shfl_xor_sync(0xffffffffu, a2, 8);
        a3 += __shfl_xor_sync(0xffffffffu, a3, 8);
        a0 += __shfl_xor_sync(0xffffffffu, a0, 16);
        a1 += __shfl_xor_sync(0xffffffffu, a1, 16);
        a2 += __shfl_xor_sync(0xffffffffu, a2, 16);
        a3 += __shfl_xor_sync(0xffffffffu, a3, 16);
        if (g == 0) {
            __nv_bfloat162 o0, o1;
            o0.x = __float2bfloat16(a0); o0.y = __float2bfloat16(a1);
            o1.x = __float2bfloat16(a2); o1.y = __float2bfloat16(a3);
            uint2 st;
            st.x = *reinterpret_cast<uint32_t*>(&o0);
            st.y = *reinterpret_cast<uint32_t*>(&o1);
            *reinterpret_cast<uint2*>(
                g_outcam + (size_t)bx * EMBED + h * DH + j * 4) = st;
        }
    }
}

// =======================================================================
// GEMM 3 (final mma): A[r][k] = invcnt[r]*sum_c outcam[c][r][k] (bf16)
// out = A @ Wout + bout + query.  M=6400, N=256, K=256.
// =======================================================================
__global__ __launch_bounds__(256) void final_mma_kernel(
    const float* __restrict__ query, const float* __restrict__ Wout,
    const float* __restrict__ bout, float* __restrict__ out)
{
    extern __shared__ char smem[];
    __nv_bfloat16* Bs = reinterpret_cast<__nv_bfloat16*>(smem);
    __nv_bfloat16* As = reinterpret_cast<__nv_bfloat16*>(smem + 128 * BP * 2);

    const int tid  = threadIdx.x;
    const int wid  = tid >> 5;
    const int lane = tid & 31;
    const int wm   = wid >> 1;
    const int wn   = wid & 1;
    const int n0   = blockIdx.x * 128;
    const int row0 = blockIdx.y * 128;
    const int qr = lane >> 2, qc = lane & 3;

#pragma unroll
    for (int i = 0; i < 64; i++) {
        int u  = i * 256 + tid;
        int k  = u >> 6;
        int np = u & 63;
        float2 w = *reinterpret_cast<const float2*>(Wout + (size_t)k * EMBED + n0 + np * 2);
        Bs[(np * 2 + 0) * BP + k] = __float2bfloat16(w.x);
        Bs[(np * 2 + 1) * BP + k] = __float2bfloat16(w.y);
    }

    float acc[2][8][4];
#pragma unroll
    for (int mi = 0; mi < 2; mi++)
#pragma unroll
        for (int ni = 0; ni < 8; ni++)
#pragma unroll
            for (int j = 0; j < 4; j++) acc[mi][ni][j] = 0.f;

    for (int kc = 0; kc < 8; kc++) {
        __syncthreads();
#pragma unroll
        for (int i = 0; i < 4; i++) {
            int u   = i * 256 + tid;
            int row = u >> 3;
            int kq  = (u & 7) * 4;
            int r = row0 + row;
            float inv = g_invcnt[r];
            float s0 = 0.f, s1 = 0.f, s2 = 0.f, s3 = 0.f;
#pragma unroll
            for (int c = 0; c < CAMS; c++) {
                const __nv_bfloat16* src =
                    g_outcam + ((size_t)c * NQ + r) * EMBED + kc * 32 + kq;
                uint2 u2 = *reinterpret_cast<const uint2*>(src);
                __nv_bfloat162 p0 = *reinterpret_cast<__nv_bfloat162*>(&u2.x);
                __nv_bfloat162 p1 = *reinterpret_cast<__nv_bfloat162*>(&u2.y);
                s0 += __bfloat162float(p0.x); s1 += __bfloat162float(p0.y);
                s2 += __bfloat162float(p1.x); s3 += __bfloat162float(p1.y);
            }
            __nv_bfloat162 q0, q1;
            q0.x = __float2bfloat16(s0 * inv); q0.y = __float2bfloat16(s1 * inv);
            q1.x = __float2bfloat16(s2 * inv); q1.y = __float2bfloat16(s3 * inv);
            uint2 st;
            st.x = *reinterpret_cast<uint32_t*>(&q0);
            st.y = *reinterpret_cast<uint32_t*>(&q1);
            *reinterpret_cast<uint2*>(&As[row * AP + kq]) = st;
        }
        __syncthreads();
        mma_chunk(As, Bs, kc, wm, wn, qr, qc, acc);
    }

#pragma unroll
    for (int mi = 0; mi < 2; mi++) {
        int rb = row0 + wm * 32 + mi * 16;
#pragma unroll
        for (int half = 0; half < 2; half++) {
            int r = rb + qr + half * 8;
            float* dst = out + (size_t)r * EMBED;
            const float* qsrc = query + (size_t)r * EMBED;
#pragma unroll
            for (int ni = 0; ni < 8; ni++) {
                int n = n0 + wn * 64 + ni * 8 + qc * 2;
                float2 qv = *reinterpret_cast<const float2*>(qsrc + n);
                float2 o;
                o.x = acc[mi][ni][half * 2 + 0] + bout[n] + qv.x;
                o.y = acc[mi][ni][half * 2 + 1] + bout[n + 1] + qv.y;
                *reinterpret_cast<float2*>(dst + n) = o;
            }
        }
    }
}

// =======================================================================
extern "C" void kernel_launch(void* const* d_in, const int* in_sizes, int n_in,
                              void* d_out, int out_size)
{
    const float* query = (const float*)d_in[0];
    /* d_in[1] = key : unused by the reference */
    const float* value = (const float*)d_in[2];
    const float* qpos  = (const float*)d_in[3];
    const float* refc  = (const float*)d_in[4];
    const unsigned int* bmask = (const unsigned int*)d_in[5];
    /* d_in[6] spatial_shapes, d_in[7] level_start_index : compile-time constants */
    const float* Wv   = (const float*)d_in[8];
    const float* bv   = (const float*)d_in[9];
    const float* Wso  = (const float*)d_in[10];
    const float* bso  = (const float*)d_in[11];
    const float* Waw  = (const float*)d_in[12];
    const float* baw  = (const float*)d_in[13];
    const float* Wout = (const float*)d_in[14];
    const float* bout = (const float*)d_in[15];
    float* out = (float*)d_out;

    cudaFuncSetAttribute(stage1_kernel,
                         cudaFuncAttributeMaxDynamicSharedMemorySize, VP_SMEM);
    cudaFuncSetAttribute(final_mma_kernel,
                         cudaFuncAttributeMaxDynamicSharedMemorySize, GM_SMEM);

    stage1_kernel   <<<S1_BLOCKS, 256, VP_SMEM>>>(value, Wv, bv,
                                                  query, qpos, Wso, bso, Waw, baw, bmask);
    sampler_kernel  <<<CAMS * NQ, 256>>>(refc);
    final_mma_kernel<<<dim3(2, 50), 256, GM_SMEM>>>(query, Wout, bout, out);
}